// round 5
// baseline (speedup 1.0000x reference)
#include <cuda_runtime.h>
#include <cstdint>

#define C_IN   8
#define C_OUT  8
#define FSZ    4
#define LLEN   65536
#define LSHIFT 16
#define BATCH  64
#define TILE   8               // output positions per thread
#define TPR    (LLEN / TILE)   // tiles per row = 8192 = 2^13

// ---- packed fp32x2 helpers (Blackwell native f32x2 pipe, PTX-only) ----
__device__ __forceinline__ void fma2(unsigned long long& d,
                                     unsigned long long a,
                                     unsigned long long b) {
    asm("fma.rn.f32x2 %0, %1, %2, %0;" : "+l"(d) : "l"(a), "l"(b));
}
__device__ __forceinline__ unsigned long long pack2(float lo, float hi) {
    unsigned long long r;
    asm("mov.b64 %0, {%1, %2};" : "=l"(r) : "f"(lo), "f"(hi));
    return r;
}
__device__ __forceinline__ void unpack2(unsigned long long v, float& lo, float& hi) {
    asm("mov.b64 {%0, %1}, %2;" : "=f"(lo), "=f"(hi) : "l"(v));
}

// Each thread computes 8 consecutive L positions for ALL 8 output channels of
// one batch row. Weights live in shared memory pre-packed as (w,w) 64-bit
// pairs; one LDS.128 fetches two filter taps (broadcast, conflict-free).
// Inner loop is pure fma.rn.f32x2: 16 FMA2 per 2 LDS.128. Input loads are
// software-pipelined one ci ahead (double buffer) to hide LDG latency within
// a ~110-register budget (no spills under __launch_bounds__(256,2)).
__global__ __launch_bounds__(256, 2)
void convPbc_1d_kernel(const float* __restrict__ x,
                       const float* __restrict__ W,
                       const float* __restrict__ bias,
                       float* __restrict__ out) {
    __shared__ __align__(16) unsigned long long ws[C_OUT][C_IN][FSZ];
    __shared__ unsigned long long bsp[C_OUT];

    int tid = threadIdx.x;
    if (tid < C_OUT * C_IN * FSZ) {
        float w = W[tid];
        int co = tid >> 5;
        int ci = (tid >> 2) & 7;
        int f  = tid & 3;
        ws[co][ci][f] = pack2(w, w);
    }
    if (tid < C_OUT) {
        float b = bias[tid];
        bsp[tid] = pack2(b, b);
    }
    __syncthreads();

    unsigned int gtid = blockIdx.x * blockDim.x + threadIdx.x;
    int b = gtid >> 13;                 // batch row
    int l = (gtid & (TPR - 1u)) << 3;   // tile start position

    const bool wrap = (l == (LLEN - TILE));
    const float* xbase = x + ((b << 3) << LSHIFT) + l;   // ci stride = LLEN

    // Double-buffered per-ci inputs: a0 = x[l..l+3], a1 = x[l+4..l+7],
    // t = (x[l+8], x[l+9], x[l+10]) with circular wrap on the last tile.
    float4 a0[2], a1[2];
    float3 t[2];

    {   // prologue: load ci = 0
        const float* xr = xbase;
        a0[0] = *reinterpret_cast<const float4*>(xr);
        a1[0] = *reinterpret_cast<const float4*>(xr + 4);
        if (!wrap) {
            float4 a2 = *reinterpret_cast<const float4*>(xr + 8);
            t[0] = make_float3(a2.x, a2.y, a2.z);
        } else {
            const float* xrow = xr - l;
            t[0] = make_float3(xrow[0], xrow[1], xrow[2]);
        }
    }

    // acc[co][j] covers positions (l+2j, l+2j+1), j = 0..3
    unsigned long long acc[C_OUT][4];
#pragma unroll
    for (int co = 0; co < C_OUT; co++) {
        unsigned long long bb = bsp[co];
        acc[co][0] = bb; acc[co][1] = bb; acc[co][2] = bb; acc[co][3] = bb;
    }

#pragma unroll
    for (int ci = 0; ci < C_IN; ci++) {
        int cur = ci & 1;
        int nxt = cur ^ 1;

        // prefetch ci+1 before computing ci
        if (ci + 1 < C_IN) {
            const float* xr = xbase + ((ci + 1) << LSHIFT);
            a0[nxt] = *reinterpret_cast<const float4*>(xr);
            a1[nxt] = *reinterpret_cast<const float4*>(xr + 4);
            if (!wrap) {
                float4 a2 = *reinterpret_cast<const float4*>(xr + 8);
                t[nxt] = make_float3(a2.x, a2.y, a2.z);
            } else {
                const float* xrow = xr - l;
                t[nxt] = make_float3(xrow[0], xrow[1], xrow[2]);
            }
        }

        // sliding pairs for ci
        unsigned long long e0 = pack2(a0[cur].x, a0[cur].y);
        unsigned long long e2 = pack2(a0[cur].z, a0[cur].w);
        unsigned long long e4 = pack2(a1[cur].x, a1[cur].y);
        unsigned long long e6 = pack2(a1[cur].z, a1[cur].w);
        unsigned long long e8 = pack2(t[cur].x,  t[cur].y);
        unsigned long long o1 = pack2(a0[cur].y, a0[cur].z);
        unsigned long long o3 = pack2(a0[cur].w, a1[cur].x);
        unsigned long long o5 = pack2(a1[cur].y, a1[cur].z);
        unsigned long long o7 = pack2(a1[cur].w, t[cur].x);
        unsigned long long o9 = pack2(t[cur].y,  t[cur].z);

#pragma unroll
        for (int co = 0; co < C_OUT; co++) {
            ulonglong2 wf01 = *reinterpret_cast<const ulonglong2*>(&ws[co][ci][0]);
            ulonglong2 wf23 = *reinterpret_cast<const ulonglong2*>(&ws[co][ci][2]);

            // tap 0
            fma2(acc[co][0], e0, wf01.x);
            fma2(acc[co][1], e2, wf01.x);
            fma2(acc[co][2], e4, wf01.x);
            fma2(acc[co][3], e6, wf01.x);
            // tap 1
            fma2(acc[co][0], o1, wf01.y);
            fma2(acc[co][1], o3, wf01.y);
            fma2(acc[co][2], o5, wf01.y);
            fma2(acc[co][3], o7, wf01.y);
            // tap 2
            fma2(acc[co][0], e2, wf23.x);
            fma2(acc[co][1], e4, wf23.x);
            fma2(acc[co][2], e6, wf23.x);
            fma2(acc[co][3], e8, wf23.x);
            // tap 3
            fma2(acc[co][0], o3, wf23.y);
            fma2(acc[co][1], o5, wf23.y);
            fma2(acc[co][2], o7, wf23.y);
            fma2(acc[co][3], o9, wf23.y);
        }
    }

#pragma unroll
    for (int co = 0; co < C_OUT; co++) {
        float r0, r1, r2, r3, r4, r5, r6, r7;
        unpack2(acc[co][0], r0, r1);
        unpack2(acc[co][1], r2, r3);
        unpack2(acc[co][2], r4, r5);
        unpack2(acc[co][3], r6, r7);
        float* orow = out + (((b << 3) + co) << LSHIFT) + l;
        *reinterpret_cast<float4*>(orow)     = make_float4(r0, r1, r2, r3);
        *reinterpret_cast<float4*>(orow + 4) = make_float4(r4, r5, r6, r7);
    }
}

extern "C" void kernel_launch(void* const* d_in, const int* in_sizes, int n_in,
                              void* d_out, int out_size) {
    const float* x    = (const float*)d_in[0];
    const float* W    = (const float*)d_in[1];
    const float* bias = (const float*)d_in[2];
    float* out        = (float*)d_out;

    const int threads = 256;
    const int blocks  = (BATCH * TPR) / threads;  // 524288 / 256 = 2048
    convPbc_1d_kernel<<<blocks, threads>>>(x, W, bias, out);
}